// round 1
// baseline (speedup 1.0000x reference)
#include <cuda_runtime.h>

#define B_ 16
#define T_ 4096
#define C_ 512
#define K_ 3
#define G_ 32
#define L_ (T_ / G_)   // 128
#define EPSV 1e-4f

// Scratch + coefficient storage (no allocations allowed).
__device__ float g_a  [K_ * C_];
__device__ float g_bb [K_ * C_];
__device__ float g_aL [K_ * C_];
__device__ float g_mix[K_ * C_];                 // mix transposed: [K][C]
__device__ float g_end  [B_ * G_ * K_ * C_];     // chunk-local end states (zero-init)
__device__ float g_carry[B_ * G_ * K_ * C_];     // exact state entering each chunk

// ---------------------------------------------------------------------------
// Pass 0: per-channel coefficients. a=clip(sigmoid), b=1-a, a^L, softmax(mix).
// ---------------------------------------------------------------------------
__global__ void coef_kernel(const float* __restrict__ logit_alpha,
                            const float* __restrict__ mix_logits) {
    int c = blockIdx.x * blockDim.x + threadIdx.x;
    if (c >= C_) return;
    #pragma unroll
    for (int k = 0; k < K_; k++) {
        float la = logit_alpha[k * C_ + c];
        float a  = 1.0f / (1.0f + __expf(-la));
        a = fminf(fmaxf(a, EPSV), 1.0f - EPSV);
        g_a [k * C_ + c] = a;
        g_bb[k * C_ + c] = 1.0f - a;
        float p = a;
        #pragma unroll
        for (int s = 0; s < 7; s++) p *= p;      // a^(2^7) = a^128 = a^L
        g_aL[k * C_ + c] = p;
    }
    float m0 = mix_logits[c * K_ + 0];
    float m1 = mix_logits[c * K_ + 1];
    float m2 = mix_logits[c * K_ + 2];
    float mx = fmaxf(m0, fmaxf(m1, m2));
    float e0 = __expf(m0 - mx), e1 = __expf(m1 - mx), e2 = __expf(m2 - mx);
    float inv = 1.0f / (e0 + e1 + e2);
    g_mix[0 * C_ + c] = e0 * inv;
    g_mix[1 * C_ + c] = e1 * inv;
    g_mix[2 * C_ + c] = e2 * inv;
}

// ---------------------------------------------------------------------------
// Pass 1: chunk-local EMA with zero initial state; store end state per chunk.
// grid = B*G blocks, block = C threads (thread = channel -> coalesced).
// ---------------------------------------------------------------------------
__global__ void __launch_bounds__(C_) pass1_kernel(const float* __restrict__ x) {
    int c  = threadIdx.x;
    int bg = blockIdx.x;
    int b  = bg / G_;
    int j  = bg % G_;

    float a0 = g_a [0 * C_ + c], a1 = g_a [1 * C_ + c], a2 = g_a [2 * C_ + c];
    float b0 = g_bb[0 * C_ + c], b1 = g_bb[1 * C_ + c], b2 = g_bb[2 * C_ + c];

    const float* xp = x + ((size_t)b * T_ + (size_t)j * L_) * C_ + c;
    float y0 = 0.0f, y1 = 0.0f, y2 = 0.0f;
    #pragma unroll 8
    for (int i = 0; i < L_; i++) {
        float xv = __ldg(xp + (size_t)i * C_);
        y0 = fmaf(a0, y0, b0 * xv);
        y1 = fmaf(a1, y1, b1 * xv);
        y2 = fmaf(a2, y2, b2 * xv);
    }
    int base = ((b * G_ + j) * K_) * C_ + c;
    g_end[base + 0 * C_] = y0;
    g_end[base + 1 * C_] = y1;
    g_end[base + 2 * C_] = y2;
}

// ---------------------------------------------------------------------------
// Pass 2: sequential scan over chunk carries. Exact: state entering chunk 0 is
// x[b,0,c] (since a*x0 + (1-a)*x0 = x0 gives y[0]=x[0]).
// grid = B*K blocks, block = C threads.
// ---------------------------------------------------------------------------
__global__ void __launch_bounds__(C_) pass2_kernel(const float* __restrict__ x) {
    int c  = threadIdx.x;
    int bk = blockIdx.x;
    int b  = bk / K_;
    int k  = bk % K_;

    float aL = g_aL[k * C_ + c];
    float s  = __ldg(x + (size_t)b * T_ * C_ + c);   // y[-1] = x[b,0,c]
    #pragma unroll
    for (int j = 0; j < G_; j++) {
        int idx = ((b * G_ + j) * K_ + k) * C_ + c;
        g_carry[idx] = s;
        s = fmaf(aL, s, g_end[idx]);
    }
}

// ---------------------------------------------------------------------------
// Pass 3: rerun the true recurrence from the exact carry-in; mix and write.
// grid = B*G blocks, block = C threads.
// ---------------------------------------------------------------------------
__global__ void __launch_bounds__(C_) pass3_kernel(const float* __restrict__ x,
                                                   float* __restrict__ out) {
    int c  = threadIdx.x;
    int bg = blockIdx.x;
    int b  = bg / G_;
    int j  = bg % G_;

    float a0 = g_a [0 * C_ + c], a1 = g_a [1 * C_ + c], a2 = g_a [2 * C_ + c];
    float b0 = g_bb[0 * C_ + c], b1 = g_bb[1 * C_ + c], b2 = g_bb[2 * C_ + c];
    float m0 = g_mix[0 * C_ + c], m1 = g_mix[1 * C_ + c], m2 = g_mix[2 * C_ + c];

    int cbase = ((b * G_ + j) * K_) * C_ + c;
    float y0 = g_carry[cbase + 0 * C_];
    float y1 = g_carry[cbase + 1 * C_];
    float y2 = g_carry[cbase + 2 * C_];

    size_t off = ((size_t)b * T_ + (size_t)j * L_) * C_ + c;
    const float* xp = x + off;
    float*       op = out + off;

    #pragma unroll 8
    for (int i = 0; i < L_; i++) {
        float xv = __ldg(xp + (size_t)i * C_);
        y0 = fmaf(a0, y0, b0 * xv);
        y1 = fmaf(a1, y1, b1 * xv);
        y2 = fmaf(a2, y2, b2 * xv);
        op[(size_t)i * C_] = fmaf(m2, y2, fmaf(m1, y1, m0 * y0));
    }
}

// ---------------------------------------------------------------------------
extern "C" void kernel_launch(void* const* d_in, const int* in_sizes, int n_in,
                              void* d_out, int out_size) {
    const float* x           = (const float*)d_in[0];
    const float* logit_alpha = (const float*)d_in[1];
    const float* mix_logits  = (const float*)d_in[2];
    float*       out         = (float*)d_out;

    coef_kernel<<<1, C_>>>(logit_alpha, mix_logits);
    pass1_kernel<<<B_ * G_, C_>>>(x);
    pass2_kernel<<<B_ * K_, C_>>>(x);
    pass3_kernel<<<B_ * G_, C_>>>(x, out);
}

// round 2
// speedup vs baseline: 1.0071x; 1.0071x over previous
#include <cuda_runtime.h>

#define B_ 16
#define T_ 4096
#define C_ 512
#define K_ 3
#define G_ 32
#define L_ (T_ / G_)   // 128
#define EPSV 1e-4f

// Scratch + coefficient storage (no allocations allowed).
__device__ float g_a  [K_ * C_];
__device__ float g_bb [K_ * C_];
__device__ float g_aL [K_ * C_];
__device__ float g_mix[K_ * C_];                 // mix transposed: [K][C]
__device__ float g_end  [B_ * G_ * K_ * C_];     // chunk-local end states (zero-init)
__device__ float g_carry[B_ * G_ * K_ * C_];     // exact state entering each chunk

// ---------------------------------------------------------------------------
// Pass 0: per-channel coefficients. a=clip(sigmoid), b=1-a, a^L, softmax(mix).
// ---------------------------------------------------------------------------
__global__ void coef_kernel(const float* __restrict__ logit_alpha,
                            const float* __restrict__ mix_logits) {
    int c = blockIdx.x * blockDim.x + threadIdx.x;
    if (c >= C_) return;
    #pragma unroll
    for (int k = 0; k < K_; k++) {
        float la = logit_alpha[k * C_ + c];
        float a  = 1.0f / (1.0f + __expf(-la));
        a = fminf(fmaxf(a, EPSV), 1.0f - EPSV);
        g_a [k * C_ + c] = a;
        g_bb[k * C_ + c] = 1.0f - a;
        float p = a;
        #pragma unroll
        for (int s = 0; s < 7; s++) p *= p;      // a^(2^7) = a^128 = a^L
        g_aL[k * C_ + c] = p;
    }
    float m0 = mix_logits[c * K_ + 0];
    float m1 = mix_logits[c * K_ + 1];
    float m2 = mix_logits[c * K_ + 2];
    float mx = fmaxf(m0, fmaxf(m1, m2));
    float e0 = __expf(m0 - mx), e1 = __expf(m1 - mx), e2 = __expf(m2 - mx);
    float inv = 1.0f / (e0 + e1 + e2);
    g_mix[0 * C_ + c] = e0 * inv;
    g_mix[1 * C_ + c] = e1 * inv;
    g_mix[2 * C_ + c] = e2 * inv;
}

// ---------------------------------------------------------------------------
// Pass 1: chunk-local EMA with zero initial state; store end state per chunk.
// grid = B*G blocks, block = C threads (thread = channel -> coalesced).
// ---------------------------------------------------------------------------
__global__ void __launch_bounds__(C_) pass1_kernel(const float* __restrict__ x) {
    int c  = threadIdx.x;
    int bg = blockIdx.x;
    int b  = bg / G_;
    int j  = bg % G_;

    float a0 = g_a [0 * C_ + c], a1 = g_a [1 * C_ + c], a2 = g_a [2 * C_ + c];
    float b0 = g_bb[0 * C_ + c], b1 = g_bb[1 * C_ + c], b2 = g_bb[2 * C_ + c];

    const float* xp = x + ((size_t)b * T_ + (size_t)j * L_) * C_ + c;
    float y0 = 0.0f, y1 = 0.0f, y2 = 0.0f;
    #pragma unroll 8
    for (int i = 0; i < L_; i++) {
        float xv = __ldg(xp + (size_t)i * C_);
        y0 = fmaf(a0, y0, b0 * xv);
        y1 = fmaf(a1, y1, b1 * xv);
        y2 = fmaf(a2, y2, b2 * xv);
    }
    int base = ((b * G_ + j) * K_) * C_ + c;
    g_end[base + 0 * C_] = y0;
    g_end[base + 1 * C_] = y1;
    g_end[base + 2 * C_] = y2;
}

// ---------------------------------------------------------------------------
// Pass 2: sequential scan over chunk carries. Exact: state entering chunk 0 is
// x[b,0,c] (since a*x0 + (1-a)*x0 = x0 gives y[0]=x[0]).
// grid = B*K blocks, block = C threads.
// ---------------------------------------------------------------------------
__global__ void __launch_bounds__(C_) pass2_kernel(const float* __restrict__ x) {
    int c  = threadIdx.x;
    int bk = blockIdx.x;
    int b  = bk / K_;
    int k  = bk % K_;

    float aL = g_aL[k * C_ + c];
    float s  = __ldg(x + (size_t)b * T_ * C_ + c);   // y[-1] = x[b,0,c]
    #pragma unroll
    for (int j = 0; j < G_; j++) {
        int idx = ((b * G_ + j) * K_ + k) * C_ + c;
        g_carry[idx] = s;
        s = fmaf(aL, s, g_end[idx]);
    }
}

// ---------------------------------------------------------------------------
// Pass 3: rerun the true recurrence from the exact carry-in; mix and write.
// grid = B*G blocks, block = C threads.
// ---------------------------------------------------------------------------
__global__ void __launch_bounds__(C_) pass3_kernel(const float* __restrict__ x,
                                                   float* __restrict__ out) {
    int c  = threadIdx.x;
    int bg = blockIdx.x;
    int b  = bg / G_;
    int j  = bg % G_;

    float a0 = g_a [0 * C_ + c], a1 = g_a [1 * C_ + c], a2 = g_a [2 * C_ + c];
    float b0 = g_bb[0 * C_ + c], b1 = g_bb[1 * C_ + c], b2 = g_bb[2 * C_ + c];
    float m0 = g_mix[0 * C_ + c], m1 = g_mix[1 * C_ + c], m2 = g_mix[2 * C_ + c];

    int cbase = ((b * G_ + j) * K_) * C_ + c;
    float y0 = g_carry[cbase + 0 * C_];
    float y1 = g_carry[cbase + 1 * C_];
    float y2 = g_carry[cbase + 2 * C_];

    size_t off = ((size_t)b * T_ + (size_t)j * L_) * C_ + c;
    const float* xp = x + off;
    float*       op = out + off;

    #pragma unroll 8
    for (int i = 0; i < L_; i++) {
        float xv = __ldg(xp + (size_t)i * C_);
        y0 = fmaf(a0, y0, b0 * xv);
        y1 = fmaf(a1, y1, b1 * xv);
        y2 = fmaf(a2, y2, b2 * xv);
        op[(size_t)i * C_] = fmaf(m2, y2, fmaf(m1, y1, m0 * y0));
    }
}

// ---------------------------------------------------------------------------
extern "C" void kernel_launch(void* const* d_in, const int* in_sizes, int n_in,
                              void* d_out, int out_size) {
    const float* x           = (const float*)d_in[0];
    const float* logit_alpha = (const float*)d_in[1];
    const float* mix_logits  = (const float*)d_in[2];
    float*       out         = (float*)d_out;

    coef_kernel<<<1, C_>>>(logit_alpha, mix_logits);
    pass1_kernel<<<B_ * G_, C_>>>(x);
    pass2_kernel<<<B_ * K_, C_>>>(x);
    pass3_kernel<<<B_ * G_, C_>>>(x, out);
}

// round 3
// speedup vs baseline: 1.3534x; 1.3438x over previous
#include <cuda_runtime.h>

#define B_ 16
#define T_ 4096
#define C_ 512
#define K_ 3
#define L_ 64
#define G_ (T_ / L_)          // 64 chunks
#define CH_ 256               // channels per block
#define NH_ (C_ / CH_)        // 2 halves
#define NCHAIN_ (B_ * NH_)    // 32 independent carry chains
#define NBLK_ (G_ * NCHAIN_)  // 2048 blocks
#define EPSV 1e-4f
#define SMEM_BYTES (L_ * CH_ * sizeof(float))   // 64 KB

// Lookback scratch (no allocations allowed -> __device__ globals).
__device__ float g_E[NBLK_ * K_ * CH_];   // chunk-local end states (zero-init recurrence)
__device__ float g_V[NBLK_ * K_ * CH_];   // inclusive prefixes (exact carry-out)
__device__ int   g_flag[NBLK_];           // 0=none, 1=E ready, 2=V ready
__device__ int   g_ticket;

// ---------------------------------------------------------------------------
__global__ void reset_kernel() {
    int i = blockIdx.x * blockDim.x + threadIdx.x;
    if (i < NBLK_) g_flag[i] = 0;
    if (i == 0) g_ticket = 0;
}

// ---------------------------------------------------------------------------
__global__ void __launch_bounds__(CH_, 3)
ema_kernel(const float* __restrict__ x,
           const float* __restrict__ logit_alpha,
           const float* __restrict__ mix_logits,
           float* __restrict__ out) {
    extern __shared__ float sx[];     // [L_][CH_], each thread uses only column tid
    __shared__ int sh_vid;
    __shared__ int sh_flag;

    const int tid = threadIdx.x;

    // Ticket: virtual block id in scheduling order (deadlock-free lookback).
    if (tid == 0) sh_vid = atomicAdd(&g_ticket, 1);
    __syncthreads();
    const int vid   = sh_vid;
    const int j     = vid / NCHAIN_;   // chunk index along T
    const int chain = vid % NCHAIN_;   // (b, half)
    const int b     = chain / NH_;
    const int half  = chain % NH_;
    const int c     = half * CH_ + tid;

    // ---- per-channel coefficients (computed locally; inputs are L2-hot) ----
    float a0, a1, a2, b0, b1, b2, aL0, aL1, aL2;
    {
        float la0 = __ldg(logit_alpha + 0 * C_ + c);
        float la1 = __ldg(logit_alpha + 1 * C_ + c);
        float la2 = __ldg(logit_alpha + 2 * C_ + c);
        a0 = 1.0f / (1.0f + __expf(-la0));
        a1 = 1.0f / (1.0f + __expf(-la1));
        a2 = 1.0f / (1.0f + __expf(-la2));
        a0 = fminf(fmaxf(a0, EPSV), 1.0f - EPSV);
        a1 = fminf(fmaxf(a1, EPSV), 1.0f - EPSV);
        a2 = fminf(fmaxf(a2, EPSV), 1.0f - EPSV);
        b0 = 1.0f - a0; b1 = 1.0f - a1; b2 = 1.0f - a2;
        aL0 = a0; aL1 = a1; aL2 = a2;
        #pragma unroll
        for (int s = 0; s < 6; s++) { aL0 *= aL0; aL1 *= aL1; aL2 *= aL2; }  // a^64
    }
    float m0, m1, m2;
    {
        float l0 = __ldg(mix_logits + c * K_ + 0);
        float l1 = __ldg(mix_logits + c * K_ + 1);
        float l2 = __ldg(mix_logits + c * K_ + 2);
        float mx = fmaxf(l0, fmaxf(l1, l2));
        float e0 = __expf(l0 - mx), e1 = __expf(l1 - mx), e2 = __expf(l2 - mx);
        float inv = 1.0f / (e0 + e1 + e2);
        m0 = e0 * inv; m1 = e1 * inv; m2 = e2 * inv;
    }

    // Exact seed: y[-1] = x[b,0,c] makes y[0] = x[0].
    const float xb0 = __ldg(x + (size_t)b * T_ * C_ + c);

    // ---- load x tile ONCE (HBM), stash in smem, compute zero-init end E ----
    const float* xp = x + ((size_t)b * T_ + (size_t)j * L_) * C_ + c;
    float y0 = 0.0f, y1 = 0.0f, y2 = 0.0f;
    #pragma unroll
    for (int ii = 0; ii < L_; ii += 16) {
        float v[16];
        #pragma unroll
        for (int u = 0; u < 16; u++) v[u] = __ldg(xp + (size_t)(ii + u) * C_);
        #pragma unroll
        for (int u = 0; u < 16; u++) {
            sx[(ii + u) * CH_ + tid] = v[u];
            y0 = fmaf(a0, y0, b0 * v[u]);
            y1 = fmaf(a1, y1, b1 * v[u]);
            y2 = fmaf(a2, y2, b2 * v[u]);
        }
    }

    // ---- publish E (flag=1) so successors can lookback immediately ----
    const int ebase = vid * (K_ * CH_) + tid;
    __stcg(&g_E[ebase + 0 * CH_], y0);
    __stcg(&g_E[ebase + 1 * CH_], y1);
    __stcg(&g_E[ebase + 2 * CH_], y2);
    __threadfence();
    __syncthreads();
    if (tid == 0) atomicExch(&g_flag[vid], 1);

    // ---- decoupled lookback: resolve exact carry-in ----
    float c0, c1, c2;
    if (j == 0) {
        c0 = xb0; c1 = xb0; c2 = xb0;
    } else {
        float acc0 = 0.0f, acc1 = 0.0f, acc2 = 0.0f;
        float p0 = 1.0f, p1 = 1.0f, p2 = 1.0f;
        int pv = vid - NCHAIN_;                       // predecessor (j-1, chain)
        while (true) {
            if (tid == 0) {
                int f;
                do {
                    f = atomicAdd(&g_flag[pv], 0);
                    if (f == 0) __nanosleep(40);
                } while (f == 0);
                sh_flag = f;
            }
            __syncthreads();
            const int f = sh_flag;
            __syncthreads();
            const float* src = (f == 2 ? g_V : g_E) + pv * (K_ * CH_) + tid;
            float e0 = __ldcg(src + 0 * CH_);
            float e1 = __ldcg(src + 1 * CH_);
            float e2 = __ldcg(src + 2 * CH_);
            if (f == 2) {                              // inclusive prefix: done
                c0 = fmaf(p0, e0, acc0);
                c1 = fmaf(p1, e1, acc1);
                c2 = fmaf(p2, e2, acc2);
                break;
            }
            acc0 = fmaf(p0, e0, acc0); p0 *= aL0;      // aggregate: keep walking
            acc1 = fmaf(p1, e1, acc1); p1 *= aL1;
            acc2 = fmaf(p2, e2, acc2); p2 *= aL2;
            pv -= NCHAIN_;
            if (pv < 0) {                              // reached the seed
                c0 = fmaf(p0, xb0, acc0);
                c1 = fmaf(p1, xb0, acc1);
                c2 = fmaf(p2, xb0, acc2);
                break;
            }
        }
    }

    // ---- publish inclusive prefix V = aL*carry + E (flag=2) ----
    __stcg(&g_V[ebase + 0 * CH_], fmaf(aL0, c0, y0));
    __stcg(&g_V[ebase + 1 * CH_], fmaf(aL1, c1, y1));
    __stcg(&g_V[ebase + 2 * CH_], fmaf(aL2, c2, y2));
    __threadfence();
    __syncthreads();
    if (tid == 0) atomicExch(&g_flag[vid], 2);

    // ---- rerun exact recurrence from carry using smem-resident x; mix; write ----
    y0 = c0; y1 = c1; y2 = c2;
    float* op = out + ((size_t)b * T_ + (size_t)j * L_) * C_ + c;
    #pragma unroll 8
    for (int i = 0; i < L_; i++) {
        float xv = sx[i * CH_ + tid];
        y0 = fmaf(a0, y0, b0 * xv);
        y1 = fmaf(a1, y1, b1 * xv);
        y2 = fmaf(a2, y2, b2 * xv);
        op[(size_t)i * C_] = fmaf(m2, y2, fmaf(m1, y1, m0 * y0));
    }
}

// ---------------------------------------------------------------------------
extern "C" void kernel_launch(void* const* d_in, const int* in_sizes, int n_in,
                              void* d_out, int out_size) {
    const float* x           = (const float*)d_in[0];
    const float* logit_alpha = (const float*)d_in[1];
    const float* mix_logits  = (const float*)d_in[2];
    float*       out         = (float*)d_out;

    static bool attr_done = false;
    if (!attr_done) {   // idempotent host-side attribute; no device work skipped
        cudaFuncSetAttribute(ema_kernel,
                             cudaFuncAttributeMaxDynamicSharedMemorySize,
                             (int)SMEM_BYTES);
        attr_done = true;
    }

    reset_kernel<<<(NBLK_ + 255) / 256, 256>>>();
    ema_kernel<<<NBLK_, CH_, SMEM_BYTES>>>(x, logit_alpha, mix_logits, out);
}